// round 9
// baseline (speedup 1.0000x reference)
#include <cuda_runtime.h>
#include <cstdint>
#include <cstddef>

// Problem: B=4, S=2048 -> TOK=8192 tokens, D=512, E=32, F=512
#define TOK   8192
#define DDIM  512
#define NEXP  32

// -------------------- device scratch --------------------
__device__ float g_gate[TOK * NEXP];   // softmax gates [t][e]
// Fragment-packed fp16 W for mma.m16n8k16:
// u32 chunks: [fb 4][dc 16][ks2 2][e 32] -> chunk of 1024 u32:
//   [wn 4][l 2][lane 32][r 4],  u32 = {lo=W[k][f], hi=W[k+1][f]}
//   k = dc*32 + ks2*16 + 2*(lane&3) + (r&1)*8
//   f = fb*128 + wn*32 + (l*2 + (r>>1))*8 + (lane>>2)
__device__ uint32_t g_wt2h[4 * 16 * 2 * 32 * 1024 + 2048];   // 16.8MB + pad

// -------------------- helpers --------------------
__device__ __forceinline__ uint32_t smem_u32(const void* p) {
    uint32_t a;
    asm("{ .reg .u64 t; cvta.to.shared.u64 t, %1; cvt.u32.u64 %0, t; }"
        : "=r"(a) : "l"(p));
    return a;
}
// pack two f32 -> f16x2 {lo, hi}  (first asm operand = hi half)
__device__ __forceinline__ uint32_t packh2(float lo, float hi) {
    uint32_t d;
    asm("cvt.rn.f16x2.f32 %0, %1, %2;" : "=r"(d) : "f"(hi), "f"(lo));
    return d;
}
__device__ __forceinline__ uint32_t hmul2(uint32_t a, uint32_t b) {
    uint32_t d;
    asm("mul.f16x2 %0, %1, %2;" : "=r"(d) : "r"(a), "r"(b));
    return d;
}
__device__ __forceinline__ void mma_f16(float* c, uint32_t a0, uint32_t a1,
                                        uint32_t a2, uint32_t a3,
                                        uint32_t b0, uint32_t b1) {
    asm volatile(
        "mma.sync.aligned.m16n8k16.row.col.f32.f16.f16.f32 "
        "{%0,%1,%2,%3}, {%4,%5,%6,%7}, {%8,%9}, {%0,%1,%2,%3};"
        : "+f"(c[0]), "+f"(c[1]), "+f"(c[2]), "+f"(c[3])
        : "r"(a0), "r"(a1), "r"(a2), "r"(a3), "r"(b0), "r"(b1));
}
#define CP_ASYNC16(dst, src) \
    asm volatile("cp.async.cg.shared.global [%0], [%1], 16;" \
        :: "r"(dst), "l"(src) : "memory")
#define CP_COMMIT() asm volatile("cp.async.commit_group;" ::: "memory")
#define CP_WAIT3()  asm volatile("cp.async.wait_group 3;" ::: "memory")

// ============ Kernel 1: fused prepass (W repack) + tensor-core gate ==========
// Blocks 0..511: prepass, e = bid & 31, dc = bid >> 5.
// Blocks 512..575: gate for tokens [ (bid-512)*128, +128 ).
#define PRE_SMEM (32 * 516 * 4)   // 66048 (covers gate's 12.5KB too)

__global__ void __launch_bounds__(256) prep_gate_kernel(
    const float* __restrict__ ew, const float* __restrict__ x,
    const float* __restrict__ gw, const float* __restrict__ gbias)
{
    extern __shared__ float ws[];
    int tid = threadIdx.x;
    int bid = blockIdx.x;

    if (bid < 512) {
        // ---------------- prepass: fragment-pack W to fp16 ----------------
        int e = bid & 31, dc = bid >> 5;
        const float4* src = reinterpret_cast<const float4*>(
            ew + ((size_t)e * DDIM + dc * 32) * DDIM);
        #pragma unroll
        for (int m = 0; m < 16; m++) {
            int v = tid + 256 * m;              // 4096 float4 = 32 rows x 128 f4
            int kk = v >> 7, fq = v & 127;
            float4 tv = src[v];
            *reinterpret_cast<float4*>(ws + kk * 516 + fq * 4) = tv;
        }
        __syncthreads();

        #pragma unroll
        for (int m = 0; m < 8; m++) {
            int v = tid + 256 * m;              // 2048 slots x uint4
            int lane = v & 31;
            int l    = (v >> 5) & 1;
            int wn   = (v >> 6) & 3;
            int ks2  = (v >> 8) & 1;
            int fb   = (v >> 9) & 3;
            int tig = lane & 3, gid = lane >> 2;
            uint32_t o[4];
            #pragma unroll
            for (int r = 0; r < 4; r++) {
                int k = ks2 * 16 + 2 * tig + (r & 1) * 8;   // within dc's 32
                int f = fb * 128 + wn * 32 + (l * 2 + (r >> 1)) * 8 + gid;
                o[r] = packh2(ws[k * 516 + f], ws[(k + 1) * 516 + f]);
            }
            size_t idx4 = ((((size_t)(fb * 16 + dc) * 2 + ks2) * 32 + e) * 256)
                        + wn * 64 + l * 32 + lane;
            reinterpret_cast<uint4*>(g_wt2h)[idx4] =
                make_uint4(o[0], o[1], o[2], o[3]);
        }
    } else {
        // ---------------- gate: fp16 MMA GEMM + softmax ----------------
        uint32_t* xsu  = reinterpret_cast<uint32_t*>(ws);          // [128][16] s20
        uint32_t* gwsu = reinterpret_cast<uint32_t*>(ws) + 128*20; // [16][32] s36
        int t0 = (bid - 512) * 128;
        int lane = tid & 31, w = tid >> 5;
        int tig = lane & 3, gid = lane >> 2;

        float acc[4][4];
        #pragma unroll
        for (int j = 0; j < 4; j++)
            #pragma unroll
            for (int q = 0; q < 4; q++) acc[j][q] = 0.f;

        #pragma unroll 1
        for (int dc = 0; dc < 16; dc++) {
            __syncthreads();
            #pragma unroll
            for (int m = 0; m < 4; m++) {
                int u = tid + 256 * m;          // 1024 float4
                int row = u >> 3, c4 = u & 7;
                float4 v = *reinterpret_cast<const float4*>(
                    x + (size_t)(t0 + row) * DDIM + dc * 32 + c4 * 4);
                xsu[row * 20 + c4 * 2]     = packh2(v.x, v.y);
                xsu[row * 20 + c4 * 2 + 1] = packh2(v.z, v.w);
            }
            {
                int kp = tid >> 4;              // 0..15
                int e2 = (tid & 15) * 2;        // 0..30
                float2 w0 = *reinterpret_cast<const float2*>(
                    gw + (size_t)(dc * 32 + 2 * kp) * NEXP + e2);
                float2 w1 = *reinterpret_cast<const float2*>(
                    gw + (size_t)(dc * 32 + 2 * kp + 1) * NEXP + e2);
                gwsu[kp * 36 + e2]     = packh2(w0.x, w1.x);
                gwsu[kp * 36 + e2 + 1] = packh2(w0.y, w1.y);
            }
            __syncthreads();

            #pragma unroll
            for (int kq = 0; kq < 2; kq++) {
                int kpb = kq * 8 + tig;
                uint32_t a0 = xsu[(w * 16 + gid) * 20 + kpb];
                uint32_t a1 = xsu[(w * 16 + gid + 8) * 20 + kpb];
                uint32_t a2 = xsu[(w * 16 + gid) * 20 + kpb + 4];
                uint32_t a3 = xsu[(w * 16 + gid + 8) * 20 + kpb + 4];
                #pragma unroll
                for (int j = 0; j < 4; j++) {
                    uint32_t b0 = gwsu[kpb * 36 + j * 8 + gid];
                    uint32_t b1 = gwsu[(kpb + 4) * 36 + j * 8 + gid];
                    mma_f16(acc[j], a0, a1, a2, a3, b0, b1);
                }
            }
        }

        // ---- bias + dual softmax (rows r0 and r0+8) + store ----
        float lr0[8], lr1[8];
        #pragma unroll
        for (int j = 0; j < 4; j++) {
            int c0 = j * 8 + tig * 2;
            float b0 = __ldg(gbias + c0), b1 = __ldg(gbias + c0 + 1);
            lr0[j * 2]     = acc[j][0] + b0;
            lr0[j * 2 + 1] = acc[j][1] + b1;
            lr1[j * 2]     = acc[j][2] + b0;
            lr1[j * 2 + 1] = acc[j][3] + b1;
        }
        float m0 = lr0[0], m1 = lr1[0];
        #pragma unroll
        for (int q = 1; q < 8; q++) {
            m0 = fmaxf(m0, lr0[q]); m1 = fmaxf(m1, lr1[q]);
        }
        #pragma unroll
        for (int o = 1; o <= 2; o <<= 1) {
            m0 = fmaxf(m0, __shfl_xor_sync(0xFFFFFFFFu, m0, o));
            m1 = fmaxf(m1, __shfl_xor_sync(0xFFFFFFFFu, m1, o));
        }
        float s0 = 0.f, s1 = 0.f;
        #pragma unroll
        for (int q = 0; q < 8; q++) {
            lr0[q] = __expf(lr0[q] - m0); s0 += lr0[q];
            lr1[q] = __expf(lr1[q] - m1); s1 += lr1[q];
        }
        #pragma unroll
        for (int o = 1; o <= 2; o <<= 1) {
            s0 += __shfl_xor_sync(0xFFFFFFFFu, s0, o);
            s1 += __shfl_xor_sync(0xFFFFFFFFu, s1, o);
        }
        float i0 = 1.0f / s0, i1 = 1.0f / s1;
        int r0 = t0 + w * 16 + gid;
        #pragma unroll
        for (int j = 0; j < 4; j++) {
            int c0 = j * 8 + tig * 2;
            *reinterpret_cast<float2*>(g_gate + (size_t)r0 * NEXP + c0) =
                make_float2(lr0[j * 2] * i0, lr0[j * 2 + 1] * i0);
            *reinterpret_cast<float2*>(g_gate + (size_t)(r0 + 8) * NEXP + c0) =
                make_float2(lr1[j * 2] * i1, lr1[j * 2 + 1] * i1);
        }
    }
}

// ======================== Kernel 2: main fp16 HMMA GEMM ======================
// grid (4 fblk, 64 tblk) = 256 CTAs, 2 CTAs/SM (one wave). 256 threads = 8
// warps, 2(M) x 4(N), warp tile 64M x 32N; CTA tile 128M x 128N.
// B path: depth-4 cp.async ring in SMEM, per-thread self-consume (each thread
// copies exactly the 32B it alone reads back) -> no syncthreads in the
// pipeline; load-to-use distance = 4 e-iters, fully covering L2 latency.
//   xsu: x staged per-dc as fp16x2 pairs [128 rows][16 kp] u32, stride 20
//   ghu: gate tile staged once as replicated fp16x2 {g,g} [128][32], stride 36
//   bsl: B ring [4 slots][256 thr][32B] = 32KB
#define XS_BYTES  (128 * 20 * 4)   // 10240
#define GH_BYTES  (128 * 36 * 4)   // 18432
#define MAIN_SMEM (XS_BYTES + GH_BYTES + 4 * 8192)   // 61440

__global__ void __launch_bounds__(256, 2) moe_main_kernel(
    const float* __restrict__ x, float* __restrict__ out)
{
    extern __shared__ uint32_t smu[];
    uint32_t* xsu = smu;                    // [128][20]
    uint32_t* ghu = smu + 128 * 20;         // [128][36]
    uint32_t xcA = smem_u32(xsu);
    uint32_t ghA_base = xcA + XS_BYTES;
    uint32_t bslA = xcA + XS_BYTES + GH_BYTES;

    int tid = threadIdx.x, lane = tid & 31, wid = tid >> 5;
    int wm = wid >> 2;              // 0..1 -> 64 rows each
    int wn = wid & 3;               // 0..3 -> 32 cols each
    int fblk = blockIdx.x;
    int t0 = blockIdx.y * 128;
    int f0 = fblk * 128;
    int tig = lane & 3, gid = lane >> 2;
    uint32_t myB = bslA + (uint32_t)tid * 32u;   // my 32B per slot

    // ---- stage gate tile as replicated fp16x2 {g,g} ----
    #pragma unroll
    for (int m = 0; m < 4; m++) {
        int u = tid + 256 * m;      // 1024 float4
        int row = u >> 3, wq = u & 7;
        float4 v = *reinterpret_cast<const float4*>(
            g_gate + (size_t)(t0 + row) * NEXP + wq * 4);
        ghu[row * 36 + wq * 4 + 0] = packh2(v.x, v.x);
        ghu[row * 36 + wq * 4 + 1] = packh2(v.y, v.y);
        ghu[row * 36 + wq * 4 + 2] = packh2(v.z, v.z);
        ghu[row * 36 + wq * 4 + 3] = packh2(v.w, v.w);
    }

    // ---- B stream: prime depth-4 cp.async ring ----
    const uint32_t* pNext = g_wt2h + (size_t)fblk * (16 * 2 * 32 * 1024)
                          + wn * 256 + lane * 4;
    const uint32_t* pLast = pNext + (size_t)1023 * 1024;   // last chunk
    #pragma unroll
    for (int s = 0; s < 4; s++) {
        CP_ASYNC16(myB + (uint32_t)s * 8192u, pNext);
        CP_ASYNC16(myB + (uint32_t)s * 8192u + 16u, pNext + 128);
        CP_COMMIT();
        pNext += 1024;
    }

    float acc[4][4][4];
    #pragma unroll
    for (int i = 0; i < 4; i++)
        #pragma unroll
        for (int j = 0; j < 4; j++)
            #pragma unroll
            for (int q = 0; q < 4; q++) acc[i][j][q] = 0.f;

    uint32_t xh[4][4];   // fp16x2 fragments for current (dc, ks2)
    uint32_t gA = ghA_base + (uint32_t)(wm * 64 + gid) * 144u;

    #pragma unroll 1
    for (int dc = 0; dc < 16; dc++) {
        __syncthreads();
        // stage x chunk as fp16x2 pairs
        #pragma unroll
        for (int m = 0; m < 4; m++) {
            int u = tid + 256 * m;      // 1024 float4
            int row = u >> 3, c4 = u & 7;
            float4 v = *reinterpret_cast<const float4*>(
                x + (size_t)(t0 + row) * DDIM + dc * 32 + c4 * 4);
            xsu[row * 20 + c4 * 2]     = packh2(v.x, v.y);
            xsu[row * 20 + c4 * 2 + 1] = packh2(v.z, v.w);
        }
        __syncthreads();

        #pragma unroll 1
        for (int ks2 = 0; ks2 < 2; ks2++) {
            // hoisted fragment loads (conflict-free: banks 20*gid+tig distinct)
            #pragma unroll
            for (int i = 0; i < 4; i++) {
                uint32_t base = xcA
                    + ((uint32_t)(wm * 64 + 16 * i + gid) * 20u
                       + (uint32_t)(ks2 * 8 + tig)) * 4u;
                asm("ld.shared.b32 %0, [%1];" : "=r"(xh[i][0]) : "r"(base));
                asm("ld.shared.b32 %0, [%1];" : "=r"(xh[i][1]) : "r"(base + 8u*20u*4u));
                asm("ld.shared.b32 %0, [%1];" : "=r"(xh[i][2]) : "r"(base + 16u));
                asm("ld.shared.b32 %0, [%1];" : "=r"(xh[i][3]) : "r"(base + 8u*20u*4u + 16u));
            }

            #pragma unroll 1
            for (int ep = 0; ep < 16; ep++) {   // e = 2*ep, unrolled x2
                // gates for both sub-iters: v2 loads (e even -> 8B aligned)
                uint32_t gg[4][4];   // [i][{g0(e),g0(e+1),g1(e),g1(e+1)}]
                #pragma unroll
                for (int i = 0; i < 4; i++) {
                    asm("ld.shared.v2.b32 {%0,%1}, [%2];"
                        : "=r"(gg[i][0]), "=r"(gg[i][1])
                        : "r"(gA + (uint32_t)(i * 16 * 144) + (uint32_t)(ep * 8)));
                    asm("ld.shared.v2.b32 {%0,%1}, [%2];"
                        : "=r"(gg[i][2]), "=r"(gg[i][3])
                        : "r"(gA + (uint32_t)(i * 16 * 144 + 8 * 144) + (uint32_t)(ep * 8)));
                }

                #pragma unroll
                for (int u = 0; u < 2; u++) {
                    int sl = (2 * ep + u) & 3;
                    uint32_t slotA = myB + (uint32_t)sl * 8192u;
                    CP_WAIT3();
                    uint4 bc0, bc1;
                    asm("ld.shared.v4.b32 {%0,%1,%2,%3}, [%4];"
                        : "=r"(bc0.x), "=r"(bc0.y), "=r"(bc0.z), "=r"(bc0.w)
                        : "r"(slotA));
                    asm("ld.shared.v4.b32 {%0,%1,%2,%3}, [%4];"
                        : "=r"(bc1.x), "=r"(bc1.y), "=r"(bc1.z), "=r"(bc1.w)
                        : "r"(slotA + 16u));
                    // refill this slot for it+4 (clamped tail re-reads last chunk)
                    if (pNext > pLast) pNext = pLast;
                    CP_ASYNC16(slotA, pNext);
                    CP_ASYNC16(slotA + 16u, pNext + 128);
                    CP_COMMIT();
                    pNext += 1024;

                    #pragma unroll
                    for (int i = 0; i < 4; i++) {
                        uint32_t a0 = hmul2(gg[i][u],     xh[i][0]);
                        uint32_t a1 = hmul2(gg[i][2 + u], xh[i][1]);
                        uint32_t a2 = hmul2(gg[i][u],     xh[i][2]);
                        uint32_t a3 = hmul2(gg[i][2 + u], xh[i][3]);
                        mma_f16(acc[i][0], a0, a1, a2, a3, bc0.x, bc0.y);
                        mma_f16(acc[i][1], a0, a1, a2, a3, bc0.z, bc0.w);
                        mma_f16(acc[i][2], a0, a1, a2, a3, bc1.x, bc1.y);
                        mma_f16(acc[i][3], a0, a1, a2, a3, bc1.z, bc1.w);
                    }
                }
            }
        }
    }

    // ---- epilogue ----
    #pragma unroll
    for (int i = 0; i < 4; i++) {
        int row = t0 + wm * 64 + 16 * i + gid;
        #pragma unroll
        for (int j = 0; j < 4; j++) {
            int col = f0 + wn * 32 + 8 * j + 2 * tig;
            *reinterpret_cast<float2*>(out + (size_t)row * DDIM + col) =
                make_float2(acc[i][j][0], acc[i][j][1]);
            *reinterpret_cast<float2*>(out + (size_t)(row + 8) * DDIM + col) =
                make_float2(acc[i][j][2], acc[i][j][3]);
        }
    }
}

// ======================== launch ========================
extern "C" void kernel_launch(void* const* d_in, const int* in_sizes, int n_in,
                              void* d_out, int out_size) {
    const float* x  = (const float*)d_in[0];   // [8192, 512]
    const float* gw = (const float*)d_in[1];   // [512, 32]
    const float* gb = (const float*)d_in[2];   // [32]
    const float* ew = (const float*)d_in[3];   // [32, 512, 512]
    float* out = (float*)d_out;                // [8192, 512]

    cudaFuncSetAttribute(prep_gate_kernel,
                         cudaFuncAttributeMaxDynamicSharedMemorySize, PRE_SMEM);
    cudaFuncSetAttribute(moe_main_kernel,
                         cudaFuncAttributeMaxDynamicSharedMemorySize, MAIN_SMEM);

    prep_gate_kernel<<<576, 256, PRE_SMEM>>>(ew, x, gw, gb);

    dim3 grid(4, 64);
    moe_main_kernel<<<grid, 256, MAIN_SMEM>>>(x, out);
}

// round 10
// speedup vs baseline: 1.7430x; 1.7430x over previous
#include <cuda_runtime.h>
#include <cstdint>
#include <cstddef>

// Problem: B=4, S=2048 -> TOK=8192 tokens, D=512, E=32, F=512
#define TOK   8192
#define DDIM  512
#define NEXP  32

// -------------------- device scratch --------------------
__device__ float g_gate[TOK * NEXP];   // softmax gates [t][e]
// Fragment-packed fp16 W for mma.m16n8k16:
// u32 chunks: [fb 4][dc 16][ks2 2][e 32] -> chunk of 1024 u32:
//   [wn 4][l 2][lane 32][r 4],  u32 = {lo=W[k][f], hi=W[k+1][f]}
//   k = dc*32 + ks2*16 + 2*(lane&3) + (r&1)*8
//   f = fb*128 + wn*32 + (l*2 + (r>>1))*8 + (lane>>2)
__device__ uint32_t g_wt2h[4 * 16 * 2 * 32 * 1024 + 2048];   // 16.8MB + pad

// -------------------- helpers --------------------
__device__ __forceinline__ uint32_t smem_u32(const void* p) {
    uint32_t a;
    asm("{ .reg .u64 t; cvta.to.shared.u64 t, %1; cvt.u32.u64 %0, t; }"
        : "=r"(a) : "l"(p));
    return a;
}
// pack two f32 -> f16x2 {lo, hi}  (first asm operand = hi half)
__device__ __forceinline__ uint32_t packh2(float lo, float hi) {
    uint32_t d;
    asm("cvt.rn.f16x2.f32 %0, %1, %2;" : "=r"(d) : "f"(hi), "f"(lo));
    return d;
}
__device__ __forceinline__ uint32_t hmul2(uint32_t a, uint32_t b) {
    uint32_t d;
    asm("mul.f16x2 %0, %1, %2;" : "=r"(d) : "r"(a), "r"(b));
    return d;
}
__device__ __forceinline__ void mma_f16(float* c, uint32_t a0, uint32_t a1,
                                        uint32_t a2, uint32_t a3,
                                        uint32_t b0, uint32_t b1) {
    asm volatile(
        "mma.sync.aligned.m16n8k16.row.col.f32.f16.f16.f32 "
        "{%0,%1,%2,%3}, {%4,%5,%6,%7}, {%8,%9}, {%0,%1,%2,%3};"
        : "+f"(c[0]), "+f"(c[1]), "+f"(c[2]), "+f"(c[3])
        : "r"(a0), "r"(a1), "r"(a2), "r"(a3), "r"(b0), "r"(b1));
}

// ============ Kernel 1: fused prepass (W repack) + tensor-core gate ==========
// Blocks 0..511: prepass, e = bid & 31, dc = bid >> 5.
// Blocks 512..575: gate for tokens [ (bid-512)*128, +128 ).
#define PRE_SMEM (32 * 516 * 4)   // 66048 (covers gate's 12.5KB too)

__global__ void __launch_bounds__(256) prep_gate_kernel(
    const float* __restrict__ ew, const float* __restrict__ x,
    const float* __restrict__ gw, const float* __restrict__ gbias)
{
    extern __shared__ float ws[];
    int tid = threadIdx.x;
    int bid = blockIdx.x;

    if (bid < 512) {
        // ---------------- prepass: fragment-pack W to fp16 ----------------
        int e = bid & 31, dc = bid >> 5;
        const float4* src = reinterpret_cast<const float4*>(
            ew + ((size_t)e * DDIM + dc * 32) * DDIM);
        #pragma unroll
        for (int m = 0; m < 16; m++) {
            int v = tid + 256 * m;              // 4096 float4 = 32 rows x 128 f4
            int kk = v >> 7, fq = v & 127;
            float4 tv = src[v];
            *reinterpret_cast<float4*>(ws + kk * 516 + fq * 4) = tv;
        }
        __syncthreads();

        #pragma unroll
        for (int m = 0; m < 8; m++) {
            int v = tid + 256 * m;              // 2048 slots x uint4
            int lane = v & 31;
            int l    = (v >> 5) & 1;
            int wn   = (v >> 6) & 3;
            int ks2  = (v >> 8) & 1;
            int fb   = (v >> 9) & 3;
            int tig = lane & 3, gid = lane >> 2;
            uint32_t o[4];
            #pragma unroll
            for (int r = 0; r < 4; r++) {
                int k = ks2 * 16 + 2 * tig + (r & 1) * 8;   // within dc's 32
                int f = fb * 128 + wn * 32 + (l * 2 + (r >> 1)) * 8 + gid;
                o[r] = packh2(ws[k * 516 + f], ws[(k + 1) * 516 + f]);
            }
            size_t idx4 = ((((size_t)(fb * 16 + dc) * 2 + ks2) * 32 + e) * 256)
                        + wn * 64 + l * 32 + lane;
            reinterpret_cast<uint4*>(g_wt2h)[idx4] =
                make_uint4(o[0], o[1], o[2], o[3]);
        }
    } else {
        // ---------------- gate: fp16 MMA GEMM + softmax ----------------
        uint32_t* xsu  = reinterpret_cast<uint32_t*>(ws);          // [128][16] s20
        uint32_t* gwsu = reinterpret_cast<uint32_t*>(ws) + 128*20; // [16][32] s36
        int t0 = (bid - 512) * 128;
        int lane = tid & 31, w = tid >> 5;
        int tig = lane & 3, gid = lane >> 2;

        float acc[4][4];
        #pragma unroll
        for (int j = 0; j < 4; j++)
            #pragma unroll
            for (int q = 0; q < 4; q++) acc[j][q] = 0.f;

        #pragma unroll 1
        for (int dc = 0; dc < 16; dc++) {
            __syncthreads();
            #pragma unroll
            for (int m = 0; m < 4; m++) {
                int u = tid + 256 * m;          // 1024 float4
                int row = u >> 3, c4 = u & 7;
                float4 v = *reinterpret_cast<const float4*>(
                    x + (size_t)(t0 + row) * DDIM + dc * 32 + c4 * 4);
                xsu[row * 20 + c4 * 2]     = packh2(v.x, v.y);
                xsu[row * 20 + c4 * 2 + 1] = packh2(v.z, v.w);
            }
            {
                int kp = tid >> 4;              // 0..15
                int e2 = (tid & 15) * 2;        // 0..30
                float2 w0 = *reinterpret_cast<const float2*>(
                    gw + (size_t)(dc * 32 + 2 * kp) * NEXP + e2);
                float2 w1 = *reinterpret_cast<const float2*>(
                    gw + (size_t)(dc * 32 + 2 * kp + 1) * NEXP + e2);
                gwsu[kp * 36 + e2]     = packh2(w0.x, w1.x);
                gwsu[kp * 36 + e2 + 1] = packh2(w0.y, w1.y);
            }
            __syncthreads();

            #pragma unroll
            for (int kq = 0; kq < 2; kq++) {
                int kpb = kq * 8 + tig;
                uint32_t a0 = xsu[(w * 16 + gid) * 20 + kpb];
                uint32_t a1 = xsu[(w * 16 + gid + 8) * 20 + kpb];
                uint32_t a2 = xsu[(w * 16 + gid) * 20 + kpb + 4];
                uint32_t a3 = xsu[(w * 16 + gid + 8) * 20 + kpb + 4];
                #pragma unroll
                for (int j = 0; j < 4; j++) {
                    uint32_t b0 = gwsu[kpb * 36 + j * 8 + gid];
                    uint32_t b1 = gwsu[(kpb + 4) * 36 + j * 8 + gid];
                    mma_f16(acc[j], a0, a1, a2, a3, b0, b1);
                }
            }
        }

        // ---- bias + dual softmax (rows r0 and r0+8) + store ----
        float lr0[8], lr1[8];
        #pragma unroll
        for (int j = 0; j < 4; j++) {
            int c0 = j * 8 + tig * 2;
            float b0 = __ldg(gbias + c0), b1 = __ldg(gbias + c0 + 1);
            lr0[j * 2]     = acc[j][0] + b0;
            lr0[j * 2 + 1] = acc[j][1] + b1;
            lr1[j * 2]     = acc[j][2] + b0;
            lr1[j * 2 + 1] = acc[j][3] + b1;
        }
        float m0 = lr0[0], m1 = lr1[0];
        #pragma unroll
        for (int q = 1; q < 8; q++) {
            m0 = fmaxf(m0, lr0[q]); m1 = fmaxf(m1, lr1[q]);
        }
        #pragma unroll
        for (int o = 1; o <= 2; o <<= 1) {
            m0 = fmaxf(m0, __shfl_xor_sync(0xFFFFFFFFu, m0, o));
            m1 = fmaxf(m1, __shfl_xor_sync(0xFFFFFFFFu, m1, o));
        }
        float s0 = 0.f, s1 = 0.f;
        #pragma unroll
        for (int q = 0; q < 8; q++) {
            lr0[q] = __expf(lr0[q] - m0); s0 += lr0[q];
            lr1[q] = __expf(lr1[q] - m1); s1 += lr1[q];
        }
        #pragma unroll
        for (int o = 1; o <= 2; o <<= 1) {
            s0 += __shfl_xor_sync(0xFFFFFFFFu, s0, o);
            s1 += __shfl_xor_sync(0xFFFFFFFFu, s1, o);
        }
        float i0 = 1.0f / s0, i1 = 1.0f / s1;
        int r0 = t0 + w * 16 + gid;
        #pragma unroll
        for (int j = 0; j < 4; j++) {
            int c0 = j * 8 + tig * 2;
            *reinterpret_cast<float2*>(g_gate + (size_t)r0 * NEXP + c0) =
                make_float2(lr0[j * 2] * i0, lr0[j * 2 + 1] * i0);
            *reinterpret_cast<float2*>(g_gate + (size_t)(r0 + 8) * NEXP + c0) =
                make_float2(lr1[j * 2] * i1, lr1[j * 2 + 1] * i1);
        }
    }
}

// ======================== Kernel 2: main fp16 HMMA GEMM ======================
// grid (4 fblk, 64 tblk) = 256 CTAs, 2 CTAs/SM (one wave). 256 threads = 8
// warps as 4(M) x 2(N); warp tile 32M x 64N; CTA tile 128M x 128N.
// vs R8 (64x32): same 16 HMMA per warp-iter but HALF the A-side prologue
// (8 HMUL2, 4 gate-LDS) and 4-way L1 dedup on B (4 wm-warps share lines).
// B double-buffered in registers via e-unroll-2 (no cp.async — L1 path).
//   xsu: x staged per-dc as fp16x2 pairs [128 rows][16 kp] u32, stride 20
//   ghu: gate tile staged once as replicated fp16x2 {g,g} [128][32], stride 36
#define MAIN_SMEM ((128 * 20 + 128 * 36) * 4)   // 28672

__global__ void __launch_bounds__(256, 2) moe_main_kernel(
    const float* __restrict__ x, float* __restrict__ out)
{
    extern __shared__ uint32_t smu[];
    uint32_t* xsu = smu;               // [128][20]
    uint32_t* ghu = smu + 128 * 20;    // [128][36]
    uint32_t xcA = smem_u32(xsu);
    uint32_t ghA_base = smem_u32(ghu);

    int tid = threadIdx.x, lane = tid & 31, wid = tid >> 5;
    int wm = wid >> 1;              // 0..3 -> 32 rows each
    int wn = wid & 1;               // 0..1 -> 64 cols each
    int fblk = blockIdx.x;
    int t0 = blockIdx.y * 128;
    int f0 = fblk * 128;
    int tig = lane & 3, gid = lane >> 2;

    // ---- stage gate tile as replicated fp16x2 {g,g} ----
    #pragma unroll
    for (int m = 0; m < 4; m++) {
        int u = tid + 256 * m;      // 1024 float4
        int row = u >> 3, wq = u & 7;
        float4 v = *reinterpret_cast<const float4*>(
            g_gate + (size_t)(t0 + row) * NEXP + wq * 4);
        ghu[row * 36 + wq * 4 + 0] = packh2(v.x, v.x);
        ghu[row * 36 + wq * 4 + 1] = packh2(v.y, v.y);
        ghu[row * 36 + wq * 4 + 2] = packh2(v.z, v.z);
        ghu[row * 36 + wq * 4 + 3] = packh2(v.w, v.w);
    }

    // ---- B stream pointer: new wn covers old wn-pair {2wn, 2wn+1} ----
    // uint4 slots per e-chunk at (wn*128 + lane) + {0, 32, 64, 96}
    const uint32_t* pB = g_wt2h + (size_t)fblk * (16 * 2 * 32 * 1024)
                       + (wn * 128 + lane) * 4;
    // double buffer A/B, e-unrolled x2
    uint4 bA0, bA1, bA2, bA3, bB0, bB1, bB2, bB3;
    bA0 = *reinterpret_cast<const uint4*>(pB);
    bA1 = *reinterpret_cast<const uint4*>(pB + 128);
    bA2 = *reinterpret_cast<const uint4*>(pB + 256);
    bA3 = *reinterpret_cast<const uint4*>(pB + 384);
    pB += 1024;

    float acc[2][8][4];
    #pragma unroll
    for (int i = 0; i < 2; i++)
        #pragma unroll
        for (int j = 0; j < 8; j++)
            #pragma unroll
            for (int q = 0; q < 4; q++) acc[i][j][q] = 0.f;

    uint32_t xh[2][4];   // fp16x2 fragments for current (dc, ks2)
    uint32_t gA = ghA_base + (uint32_t)(wm * 32 + gid) * 144u;

    #pragma unroll 1
    for (int dc = 0; dc < 16; dc++) {
        __syncthreads();
        // stage x chunk as fp16x2 pairs
        #pragma unroll
        for (int m = 0; m < 4; m++) {
            int u = tid + 256 * m;      // 1024 float4
            int row = u >> 3, c4 = u & 7;
            float4 v = *reinterpret_cast<const float4*>(
                x + (size_t)(t0 + row) * DDIM + dc * 32 + c4 * 4);
            xsu[row * 20 + c4 * 2]     = packh2(v.x, v.y);
            xsu[row * 20 + c4 * 2 + 1] = packh2(v.z, v.w);
        }
        __syncthreads();

        #pragma unroll 1
        for (int ks2 = 0; ks2 < 2; ks2++) {
            // hoisted fragment loads (conflict-free: banks 20*gid+tig distinct)
            #pragma unroll
            for (int i = 0; i < 2; i++) {
                uint32_t base = xcA
                    + ((uint32_t)(wm * 32 + 16 * i + gid) * 20u
                       + (uint32_t)(ks2 * 8 + tig)) * 4u;
                asm("ld.shared.b32 %0, [%1];" : "=r"(xh[i][0]) : "r"(base));
                asm("ld.shared.b32 %0, [%1];" : "=r"(xh[i][1]) : "r"(base + 8u*20u*4u));
                asm("ld.shared.b32 %0, [%1];" : "=r"(xh[i][2]) : "r"(base + 16u));
                asm("ld.shared.b32 %0, [%1];" : "=r"(xh[i][3]) : "r"(base + 8u*20u*4u + 16u));
            }

            #pragma unroll 1
            for (int ep = 0; ep < 16; ep++) {   // e = 2*ep (buf A), 2*ep+1 (buf B)
                // load buf B for e+1 while consuming buf A (e)
                bB0 = *reinterpret_cast<const uint4*>(pB);
                bB1 = *reinterpret_cast<const uint4*>(pB + 128);
                bB2 = *reinterpret_cast<const uint4*>(pB + 256);
                bB3 = *reinterpret_cast<const uint4*>(pB + 384);
                pB += 1024;
                {
                    int e = 2 * ep;
                    #pragma unroll
                    for (int i = 0; i < 2; i++) {
                        uint32_t g0, g1;
                        asm("ld.shared.b32 %0, [%1];" : "=r"(g0)
                            : "r"(gA + (uint32_t)(i * 16 * 144 + e * 4)));
                        asm("ld.shared.b32 %0, [%1];" : "=r"(g1)
                            : "r"(gA + (uint32_t)(i * 16 * 144 + 8 * 144 + e * 4)));
                        uint32_t a0 = hmul2(g0, xh[i][0]);
                        uint32_t a1 = hmul2(g1, xh[i][1]);
                        uint32_t a2 = hmul2(g0, xh[i][2]);
                        uint32_t a3 = hmul2(g1, xh[i][3]);
                        mma_f16(acc[i][0], a0, a1, a2, a3, bA0.x, bA0.y);
                        mma_f16(acc[i][1], a0, a1, a2, a3, bA0.z, bA0.w);
                        mma_f16(acc[i][2], a0, a1, a2, a3, bA1.x, bA1.y);
                        mma_f16(acc[i][3], a0, a1, a2, a3, bA1.z, bA1.w);
                        mma_f16(acc[i][4], a0, a1, a2, a3, bA2.x, bA2.y);
                        mma_f16(acc[i][5], a0, a1, a2, a3, bA2.z, bA2.w);
                        mma_f16(acc[i][6], a0, a1, a2, a3, bA3.x, bA3.y);
                        mma_f16(acc[i][7], a0, a1, a2, a3, bA3.z, bA3.w);
                    }
                }
                // load buf A for e+2 while consuming buf B (e+1)
                // (tail overrun of one 4KB chunk is covered by g_wt2h pad)
                bA0 = *reinterpret_cast<const uint4*>(pB);
                bA1 = *reinterpret_cast<const uint4*>(pB + 128);
                bA2 = *reinterpret_cast<const uint4*>(pB + 256);
                bA3 = *reinterpret_cast<const uint4*>(pB + 384);
                pB += 1024;
                {
                    int e = 2 * ep + 1;
                    #pragma unroll
                    for (int i = 0; i < 2; i++) {
                        uint32_t g0, g1;
                        asm("ld.shared.b32 %0, [%1];" : "=r"(g0)
                            : "r"(gA + (uint32_t)(i * 16 * 144 + e * 4)));
                        asm("ld.shared.b32 %0, [%1];" : "=r"(g1)
                            : "r"(gA + (uint32_t)(i * 16 * 144 + 8 * 144 + e * 4)));
                        uint32_t a0 = hmul2(g0, xh[i][0]);
                        uint32_t a1 = hmul2(g1, xh[i][1]);
                        uint32_t a2 = hmul2(g0, xh[i][2]);
                        uint32_t a3 = hmul2(g1, xh[i][3]);
                        mma_f16(acc[i][0], a0, a1, a2, a3, bB0.x, bB0.y);
                        mma_f16(acc[i][1], a0, a1, a2, a3, bB0.z, bB0.w);
                        mma_f16(acc[i][2], a0, a1, a2, a3, bB1.x, bB1.y);
                        mma_f16(acc[i][3], a0, a1, a2, a3, bB1.z, bB1.w);
                        mma_f16(acc[i][4], a0, a1, a2, a3, bB2.x, bB2.y);
                        mma_f16(acc[i][5], a0, a1, a2, a3, bB2.z, bB2.w);
                        mma_f16(acc[i][6], a0, a1, a2, a3, bB3.x, bB3.y);
                        mma_f16(acc[i][7], a0, a1, a2, a3, bB3.z, bB3.w);
                    }
                }
            }
        }
    }

    // ---- epilogue ----
    #pragma unroll
    for (int i = 0; i < 2; i++) {
        int row = t0 + wm * 32 + 16 * i + gid;
        #pragma unroll
        for (int j = 0; j < 8; j++) {
            int col = f0 + wn * 64 + 8 * j + 2 * tig;
            *reinterpret_cast<float2*>(out + (size_t)row * DDIM + col) =
                make_float2(acc[i][j][0], acc[i][j][1]);
            *reinterpret_cast<float2*>(out + (size_t)(row + 8) * DDIM + col) =
                make_float2(acc[i][j][2], acc[i][j][3]);
        }
    }
}

// ======================== launch ========================
extern "C" void kernel_launch(void* const* d_in, const int* in_sizes, int n_in,
                              void* d_out, int out_size) {
    const float* x  = (const float*)d_in[0];   // [8192, 512]
    const float* gw = (const float*)d_in[1];   // [512, 32]
    const float* gb = (const float*)d_in[2];   // [32]
    const float* ew = (const float*)d_in[3];   // [32, 512, 512]
    float* out = (float*)d_out;                // [8192, 512]

    cudaFuncSetAttribute(prep_gate_kernel,
                         cudaFuncAttributeMaxDynamicSharedMemorySize, PRE_SMEM);
    cudaFuncSetAttribute(moe_main_kernel,
                         cudaFuncAttributeMaxDynamicSharedMemorySize, MAIN_SMEM);

    prep_gate_kernel<<<576, 256, PRE_SMEM>>>(ew, x, gw, gb);

    dim3 grid(4, 64);
    moe_main_kernel<<<grid, 256, MAIN_SMEM>>>(x, out);
}